// round 17
// baseline (speedup 1.0000x reference)
#include <cuda_runtime.h>
#include <math.h>
#include <stdint.h>

#define NTOK   20
#define DVEC   256
#define KSAMP  4096
#define NSTEP  19
#define SPB    4                 /* samples per block */
#define NBLK   (KSAMP/SPB)       /* 1024 blocks */
#define TPB    256               /* 8 warps */
#define GPW    (NSTEP*NTOK)      /* 380 keys per sample */

__device__ float          g_S[NTOK*6];   // [i][0..2]=x.Wf+b, [3..5]=x.Wa
__device__ float          g_score[KSAMP];
__device__ unsigned char  g_legal[KSAMP];
__device__ unsigned int   g_gmax_u = 0;       // int-mapped float max (reset)
__device__ int            g_cnt = 0;          // legal count (reset)
__device__ int            g_prep_done = 0;    // reset by last block
__device__ int            g_blocks_done = 0;  // reset by last block

// ---------------- Threefry-2x32 (20 rounds), identical to JAX ----------------
__host__ __device__ __forceinline__ void tf_block(uint32_t k0, uint32_t k1,
                                                  uint32_t x0, uint32_t x1,
                                                  uint32_t* o0, uint32_t* o1) {
  uint32_t ks2 = k0 ^ k1 ^ 0x1BD11BDAu;
  x0 += k0; x1 += k1;
#define TF_ROT(r) { x0 += x1; x1 = (x1 << (r)) | (x1 >> (32 - (r))); x1 ^= x0; }
  TF_ROT(13) TF_ROT(15) TF_ROT(26) TF_ROT(6)
  x0 += k1;  x1 += ks2 + 1u;
  TF_ROT(17) TF_ROT(29) TF_ROT(16) TF_ROT(24)
  x0 += ks2; x1 += k0 + 2u;
  TF_ROT(13) TF_ROT(15) TF_ROT(26) TF_ROT(6)
  x0 += k0;  x1 += k1 + 3u;
  TF_ROT(17) TF_ROT(29) TF_ROT(16) TF_ROT(24)
  x0 += k1;  x1 += ks2 + 4u;
  TF_ROT(13) TF_ROT(15) TF_ROT(26) TF_ROT(6)
  x0 += ks2; x1 += k0 + 5u;
#undef TF_ROT
  *o0 = x0; *o1 = x1;
}

__device__ __forceinline__ uint32_t tf_bits32(uint32_t k0, uint32_t k1, uint32_t i) {
  uint32_t a, b;
  tf_block(k0, k1, 0u, i, &a, &b);
  return a ^ b;
}

// ---------------- warp-per-token prep (lane owns 8 dims, shuffle-only) --------
__device__ __forceinline__ void prep_token(int i, int lane,
                                           const int* __restrict__ ids,
                                           const float* __restrict__ emb,
                                           const float* __restrict__ lv,
                                           const float* __restrict__ fx,
                                           const float* __restrict__ Wf,
                                           const float* __restrict__ Wa,
                                           const float* __restrict__ bop) {
  const unsigned FULL = 0xFFFFFFFFu;
  int id = ids[i];
  const float4* er = (const float4*)(emb + (size_t)id * DVEC);
  const float4* fr = (const float4*)(fx  + (size_t)id * DVEC);
  float4 e0 = er[lane * 2], e1 = er[lane * 2 + 1];
  float4 f0 = fr[lane * 2], f1 = fr[lane * 2 + 1];
  float lvv = lv[id];

  float ev[8] = {e0.x, e0.y, e0.z, e0.w, e1.x, e1.y, e1.z, e1.w};
  float fv[8] = {f0.x, f0.y, f0.z, f0.w, f1.x, f1.y, f1.z, f1.w};

  float m = ev[0];
#pragma unroll
  for (int j = 1; j < 8; j++) m = fmaxf(m, ev[j]);
#pragma unroll
  for (int o = 16; o; o >>= 1) m = fmaxf(m, __shfl_xor_sync(FULL, m, o));

  float ex[8]; float sm = 0.0f;
#pragma unroll
  for (int j = 0; j < 8; j++) { ex[j] = expf(ev[j] - m); sm += ex[j]; }
#pragma unroll
  for (int o = 16; o; o >>= 1) sm += __shfl_xor_sync(FULL, sm, o);

  float x[8];
#pragma unroll
  for (int j = 0; j < 8; j++) x[j] = (ex[j] / sm) * lvv + fv[j];

  float p[6] = {0, 0, 0, 0, 0, 0};
#pragma unroll
  for (int j = 0; j < 8; j++) {
    int d = lane * 8 + j;
    p[0] += x[j] * Wf[d * 3 + 0];
    p[1] += x[j] * Wf[d * 3 + 1];
    p[2] += x[j] * Wf[d * 3 + 2];
    p[3] += x[j] * Wa[d * 3 + 0];
    p[4] += x[j] * Wa[d * 3 + 1];
    p[5] += x[j] * Wa[d * 3 + 2];
  }
#pragma unroll
  for (int o = 16; o; o >>= 1) {
#pragma unroll
    for (int q = 0; q < 6; q++) p[q] += __shfl_xor_sync(FULL, p[q], o);
  }
  if (lane == 0) {
#pragma unroll
    for (int q = 0; q < 6; q++)
      g_S[i * 6 + q] = p[q] + (q < 3 ? bop[q] : 0.0f);
    __threadfence();
    atomicAdd(&g_prep_done, 1);
  }
}

// ---------------- single fused kernel: coop keygen + 4-lane-merge scan --------
__global__ __launch_bounds__(TPB) void fused_all(
    uint32_t kop0, uint32_t kop1, uint32_t kg0, uint32_t kg1,
    const int* __restrict__ ids, const float* __restrict__ emb,
    const float* __restrict__ lv, const float* __restrict__ fx,
    const float* __restrict__ Wf, const float* __restrict__ Wa,
    const float* __restrict__ bop, float* __restrict__ out) {
  __shared__ uint32_t      skey[SPB][384];   // 380 used + 4 pad per sample
  __shared__ unsigned char ops_s[SPB][20];
  __shared__ float         sS[NTOK * 6];
  __shared__ float         sred[TPB];

  const unsigned FULL = 0xFFFFFFFFu;
  int tid = threadIdx.x;
  int lane = tid & 31, w = tid >> 5;
  int k0b = blockIdx.x * SPB;

  // blocks 0..19, warp 0: prep one token (overlaps everyone's keygen)
  if (blockIdx.x < NTOK && w == 0)
    prep_token(blockIdx.x, lane, ids, emb, lv, fx, Wf, Wa, bop);

  // warps 4..7: ops for sample (w-4); lane t in [0,20) computes op_t
  if (w >= 4 && lane < 20) {
    int si = w - 4;
    uint32_t bits = tf_bits32(kop0, kop1, (uint32_t)(lane * KSAMP + k0b + si));
    uint32_t op = ((bits >> 16) % 3u + (bits & 0xFFFFu) % 3u) % 3u;
    ops_s[si][lane] = (unsigned char)op;
  }

  // ---- keygen: all 8 warps, 6 hashes per thread, explicitly interleaved ----
  {
    uint32_t a0[6], a1[6], jj[6];
#pragma unroll
    for (int r = 0; r < 6; r++) {
      int f = tid + TPB * r;
      int si = f / 384, l = f - si * 384;
      int t = l / 20, j = l - t * 20;
      jj[r] = (uint32_t)j;
      uint32_t ctr = (uint32_t)t * 81920u + (uint32_t)(k0b + si) * 20u + (uint32_t)j;
      a0[r] = kg0;                 // x0 = 0 + k0
      a1[r] = ctr + kg1;           // x1 = ctr + k1
    }
    uint32_t ks2 = kg0 ^ kg1 ^ 0x1BD11BDAu;
#define R6(rot) _Pragma("unroll") for (int r = 0; r < 6; r++) { \
      a0[r] += a1[r]; a1[r] = (a1[r] << (rot)) | (a1[r] >> (32 - (rot))); a1[r] ^= a0[r]; }
#define INJ6(ka, kb, c) { uint32_t kb_c = (kb) + (c); \
      _Pragma("unroll") for (int r = 0; r < 6; r++) { \
      a0[r] += (ka); a1[r] += kb_c; } }
    R6(13) R6(15) R6(26) R6(6)   INJ6(kg1, ks2, 1u)
    R6(17) R6(29) R6(16) R6(24)  INJ6(ks2, kg0, 2u)
    R6(13) R6(15) R6(26) R6(6)   INJ6(kg0, kg1, 3u)
    R6(17) R6(29) R6(16) R6(24)  INJ6(kg1, ks2, 4u)
    R6(13) R6(15) R6(26) R6(6)   INJ6(ks2, kg0, 5u)
#undef R6
#undef INJ6
#pragma unroll
    for (int r = 0; r < 6; r++) {
      int f = tid + TPB * r;
      int si = f / 384, l = f - si * 384;
      uint32_t key = (a0[r] ^ a1[r]) >> 9;   // gumbel order == bits>>9
      skey[si][l] = ((key + 1u) << 5) | (31u - jj[r]);
    }
  }

  // block-level wait for the 20 prep warps, then stage sS
  if (tid == 0) {
    while (*((volatile int*)&g_prep_done) != NTOK) __nanosleep(40);
  }
  __syncthreads();
  __threadfence();                       // acquire g_S
  if (tid < NTOK * 6) sS[tid] = g_S[tid];
  __syncthreads();

  // ---- warp 0: scan 4 samples with 4 lanes each (R10-proven merge) ----
  if (w == 0) {
    int samp8 = lane >> 2;               // 0..7 (4..7 duplicate)
    int si = samp8 & 3;                  // sample-in-block (dup for hi lanes)
    bool real = samp8 < 4;
    int s = lane & 3;                    // sub-lane 0..3
    int j0 = s * 5;

    uint32_t ow[5];
    {
      const uint32_t* p = (const uint32_t*)ops_s[si];
#pragma unroll
      for (int q = 0; q < 5; q++) ow[q] = p[q];
    }

    unsigned avail = 0xFFFFFu, f1 = 0u, f2 = 0u;
    unsigned long long plo = 0ull, phi = 0ull;   // ptr[20], 5 bits/slot
#pragma unroll
    for (int j = 0; j < 12; j++) plo |= (unsigned long long)j << (5 * j);
#pragma unroll
    for (int j = 12; j < 20; j++) phi |= (unsigned long long)j << (5 * (j - 12));

    float score = 0.0f;
    bool legal = true;

#pragma unroll
    for (int t = 0; t < NSTEP; t++) {
      // local masked top-2 over 5 owned slots (packed keys: exact tie-break)
      uint32_t u1 = 0u, u2 = 0u;
#pragma unroll
      for (int i = 0; i < 5; i++) {
        uint32_t v = ((avail >> (j0 + i)) & 1u) ? skey[si][t * 20 + j0 + i] : 0u;
        uint32_t mn = min(u1, v);
        u1 = max(u1, v);
        u2 = max(u2, mn);
      }
      // merge across the 4 sub-lanes (xor 1,2 stay within the group)
#pragma unroll
      for (int o = 1; o <= 2; o <<= 1) {
        uint32_t o1 = __shfl_xor_sync(FULL, u1, o);
        uint32_t o2 = __shfl_xor_sync(FULL, u2, o);
        uint32_t lo = min(u1, o1);
        u1 = max(u1, o1);
        u2 = max(lo, max(u2, o2));
      }
      int b1 = (int)((~u1) & 31u), b2 = (int)((~u2) & 31u);
      avail &= ~(1u << b2);

      int op = (int)((ow[t >> 2] >> ((t & 3) * 8)) & 3u);

      int s1 = 5 * b1, s2s = 5 * b2;
      int s1l = (s1 < 60) ? s1 : 0,  s1h = (s1 >= 60) ? s1 - 60 : 0;
      int s2l = (s2s < 60) ? s2s : 0, s2h = (s2s >= 60) ? s2s - 60 : 0;
      int pf = (int)((b1 < 12 ? (plo >> s1l) : (phi >> s1h)) & 31ull);
      int pa = (int)((b2 < 12 ? (plo >> s2l) : (phi >> s2h)) & 31ull);
      if (s == 0) score += sS[pf * 6 + op] + sS[pa * 6 + 3 + op];

      unsigned of1 = (f1 >> b1) & 1u;
      unsigned of2 = (f2 >> b1) & 1u;
      bool bad = ((op != 2) && of1) || ((op == 1) && of2);
      legal = legal && !bad;

      if (op == 2) {                     // mod: slot b1 := copy of slot b2
        if (b1 < 12) plo = (plo & ~(31ull << s1l)) | ((unsigned long long)pa << s1l);
        else         phi = (phi & ~(31ull << s1h)) | ((unsigned long long)pa << s1h);
        unsigned a1 = (f1 >> b2) & 1u, a2 = (f2 >> b2) & 1u;
        f1 = (f1 & ~(1u << b1)) | (a1 << b1);
        f2 = (f2 & ~(1u << b1)) | (a2 << b1);
      } else if (op == 0) {
        f1 |= 1u << b1;
      } else {
        f2 |= 1u << b1;
      }
    }

    if (s == 0 && real) {
      g_score[k0b + si] = score;
      g_legal[k0b + si] = legal ? 1 : 0;
      __threadfence();                   // writer-side fence (per-thread)
    }
    __syncwarp();

    // warp partials (one contribution per real sample)
    float lm = (s == 0 && real && legal) ? score : -INFINITY;
    int lc = (s == 0 && real && legal) ? 1 : 0;
#pragma unroll
    for (int o = 16; o; o >>= 1) {
      lm = fmaxf(lm, __shfl_xor_sync(FULL, lm, o));
      lc += __shfl_xor_sync(FULL, lc, o);
    }
    if (lane == 0) {
      if (lc > 0) {
        int sv = __float_as_int(lm);
        unsigned enc = (unsigned)sv ^ (((unsigned)(sv >> 31)) | 0x80000000u);
        atomicMax(&g_gmax_u, enc);
      }
      atomicAdd(&g_cnt, lc);
      __threadfence();
      int last = (atomicAdd(&g_blocks_done, 1) == NBLK - 1);
      sred[0] = (float)last;
    }
  }
  __syncthreads();
  if (sred[0] == 0.0f) return;
  __threadfence();                       // acquire scores/legal/max/cnt

  unsigned genc = g_gmax_u;
  int cnt = g_cnt;
  int gs = (genc & 0x80000000u) ? (int)(genc ^ 0x80000000u) : (int)(~genc);
  float gm = __int_as_float(gs);

  float sum = 0.0f;
  int q0 = tid * (KSAMP / TPB);          // 16 samples per thread
#pragma unroll
  for (int q = 0; q < KSAMP / TPB; q += 4) {
    float4 sc = *(const float4*)(g_score + q0 + q);
    uchar4 lg = *(const uchar4*)(g_legal + q0 + q);
    if (lg.x) sum += __expf(sc.x - gm);
    if (lg.y) sum += __expf(sc.y - gm);
    if (lg.z) sum += __expf(sc.z - gm);
    if (lg.w) sum += __expf(sc.w - gm);
  }
  __syncthreads();
  sred[tid] = sum; __syncthreads();
  for (int st = TPB / 2; st > 0; st >>= 1) {
    if (tid < st) sred[tid] += sred[tid + st];
    __syncthreads();
  }

  if (tid == 0) {
    float lse = gm + logf(sred[0]);
    double log_all = lgamma(21.0) + log(1767263190.0) + 19.0 * log(3.0);
    double res = log_all + (double)logf((float)cnt) - 2.0 * log(4096.0) + (double)lse;
    out[0] = (float)res;
    g_blocks_done = 0;                   // reset for next graph replay
    g_cnt = 0;
    g_gmax_u = 0u;
    g_prep_done = 0;
  }
}

// ---------------- Launch ------------------------------------------------------
extern "C" void kernel_launch(void* const* d_in, const int* in_sizes, int n_in,
                              void* d_out, int out_size) {
  const int*   ids = (const int*)d_in[0];
  const float* emb = (const float*)d_in[1];
  const float* lv  = (const float*)d_in[2];
  const float* fx  = (const float*)d_in[3];
  const float* Wf  = (const float*)d_in[4];
  const float* Wa  = (const float*)d_in[5];
  const float* bop = (const float*)d_in[6];
  float* out = (float*)d_out;

  // jax.random.key(42) -> (0,42); partitionable foldlike split
  uint32_t kop0, kop1, kg0, kg1;
  tf_block(0u, 42u, 0u, 0u, &kop0, &kop1);
  tf_block(0u, 42u, 0u, 1u, &kg0, &kg1);

  fused_all<<<NBLK, TPB>>>(kop0, kop1, kg0, kg1,
                           ids, emb, lv, fx, Wf, Wa, bop, out);
}